// round 1
// baseline (speedup 1.0000x reference)
#include <cuda_runtime.h>
#include <math.h>

#define BB 2
#define NN 4096
#define HH 64
#define INDIM 32
#define OUTDIM 8
#define ROWS (BB*NN)

// ---------------- device scratch (static, allocation-free) ----------------
__device__ float g_qn[3][ROWS*HH];   // normalized queries per successor type
__device__ float g_kn[6][ROWS*HH];   // normalized keys per edge
__device__ float g_acc[3][ROWS*HH];  // accumulated attention per type

// ============================================================
// Kernel 1: q/k projections + row L2-normalize
// jobs 0..2: q_t = normalize(h_t @ Wq[t]^T)
// jobs 3..8: k_e = normalize(h_pred(e) @ Wk[e]^T)
// ============================================================
__global__ void proj_norm_kernel(const float* __restrict__ h0,
                                 const float* __restrict__ h1,
                                 const float* __restrict__ h2,
                                 const float* __restrict__ Wq,
                                 const float* __restrict__ Wk) {
    __shared__ float sH[64][65];
    __shared__ float sW[64][65];
    int job = blockIdx.y;
    const float* hs;
    const float* W;
    float* dst;
    if (job < 3) {
        hs = (job == 0) ? h0 : (job == 1 ? h1 : h2);
        W = Wq + job * HH * HH;
        dst = g_qn[job];
    } else {
        int e = job - 3;
        // edge preds: e0:h0 e1:h2 e2:h0 e3:h1 e4:h1 e5:h2
        int pred = (e == 0 || e == 2) ? 0 : ((e == 3 || e == 4) ? 1 : 2);
        hs = (pred == 0) ? h0 : (pred == 1 ? h1 : h2);
        W = Wk + e * HH * HH;
        dst = g_kn[e];
    }
    int row0 = blockIdx.x * 64;
    int tid = threadIdx.x;
    for (int i = tid; i < 64 * 64; i += 256) {
        int r = i >> 6, c = i & 63;
        sH[r][c] = hs[(size_t)(row0 + r) * HH + c];
        sW[r][c] = W[i];
    }
    __syncthreads();
    int ty = tid >> 4, tx = tid & 15;
    float acc[4][4] = {};
#pragma unroll 8
    for (int k = 0; k < 64; k++) {
        float a[4], bv[4];
#pragma unroll
        for (int i = 0; i < 4; i++) a[i] = sH[ty * 4 + i][k];
#pragma unroll
        for (int j = 0; j < 4; j++) bv[j] = sW[tx * 4 + j][k];
#pragma unroll
        for (int i = 0; i < 4; i++)
#pragma unroll
            for (int j = 0; j < 4; j++)
                acc[i][j] = fmaf(a[i], bv[j], acc[i][j]);
    }
    // row-norm: each row's 64 cols live in the 16 lanes sharing ty
    float ss[4];
#pragma unroll
    for (int i = 0; i < 4; i++)
        ss[i] = acc[i][0] * acc[i][0] + acc[i][1] * acc[i][1] +
                acc[i][2] * acc[i][2] + acc[i][3] * acc[i][3];
#pragma unroll
    for (int off = 8; off >= 1; off >>= 1) {
#pragma unroll
        for (int i = 0; i < 4; i++)
            ss[i] += __shfl_xor_sync(0xffffffffu, ss[i], off);
    }
#pragma unroll
    for (int i = 0; i < 4; i++) {
        float inv = rsqrtf(ss[i]);
#pragma unroll
        for (int j = 0; j < 4; j++)
            dst[(size_t)(row0 + ty * 4 + i) * HH + tx * 4 + j] = acc[i][j] * inv;
    }
}

// ============================================================
// Kernel 2: masked cosine attention, both edges of one type fused.
// acc_t[b, n, :] = sum_e (1/cnt_e[n]) * sum_m mask_e[n,m]*(qn.kn)*v_e[m,:]
// Block: 256 thr, BM=64 query rows, sweep 64-key tiles, 4x4 reg tiles.
// smem k-major staging -> float4 LDS, FMA-issue-bound.
// ============================================================
__global__ void attn_kernel(const float* __restrict__ h0,
                            const float* __restrict__ h1,
                            const float* __restrict__ h2,
                            const float* __restrict__ m00, const float* __restrict__ m20,
                            const float* __restrict__ m01, const float* __restrict__ m11,
                            const float* __restrict__ m12, const float* __restrict__ m22) {
    extern __shared__ float sm[];
    float* sQt = sm;                 // [d][r]  64x68
    float* sKt = sm + 64 * 68;       // [d][c]  64x68
    float* sMt = sm + 2 * 64 * 68;   // [c][r]  64x68  (mask^T, then masked-S^T)
    float* sV  = sm + 3 * 64 * 68;   // [c][h]  64x64

    int t = blockIdx.y, b = blockIdx.z;
    int row0 = blockIdx.x * 64;
    int tid = threadIdx.x, ty = tid >> 4, tx = tid & 15;

    const float* vtab[6] = {h0, h2, h0, h1, h1, h2};
    const float* mtab[6] = {m00, m20, m01, m11, m12, m22};

    const float* q = g_qn[t] + (size_t)b * NN * HH;
    for (int i = tid; i < 64 * 64; i += 256) {
        int r = i >> 6, d = i & 63;
        sQt[d * 68 + r] = q[(size_t)(row0 + r) * HH + d];
    }

    float o[4][4] = {};
    for (int ee = 0; ee < 2; ee++) {
        int e = 2 * t + ee;
        const float* kn = g_kn[e] + (size_t)b * NN * HH;
        const float* v  = vtab[e] + (size_t)b * NN * HH;
        const float* M  = mtab[e];   // [N][N], shared across batch
        float po[4][4] = {};
        float cnt[4] = {};
        for (int kt = 0; kt < 64; kt++) {
            int m0 = kt * 64;
            __syncthreads();   // protect prev tile's smem readers
            for (int i = tid; i < 64 * 64; i += 256) {
                int c = i >> 6, d = i & 63;
                float kv = kn[(size_t)(m0 + c) * HH + d];
                sKt[d * 68 + c] = kv;
                sV[c * 64 + d] = v[(size_t)(m0 + c) * HH + d];
            }
            for (int i = tid; i < 64 * 64; i += 256) {
                int r = i >> 6, c = i & 63;
                sMt[c * 68 + r] = M[(size_t)(row0 + r) * NN + m0 + c];
            }
            __syncthreads();
            // S = Qn @ Kn^T  (64x64), per-thread 4x4
            float s[4][4] = {};
#pragma unroll 8
            for (int d = 0; d < 64; d++) {
                float4 a  = *(const float4*)&sQt[d * 68 + ty * 4];
                float4 bb = *(const float4*)&sKt[d * 68 + tx * 4];
                float ar[4] = {a.x, a.y, a.z, a.w};
                float bc[4] = {bb.x, bb.y, bb.z, bb.w};
#pragma unroll
                for (int i = 0; i < 4; i++)
#pragma unroll
                    for (int j = 0; j < 4; j++)
                        s[i][j] = fmaf(ar[i], bc[j], s[i][j]);
            }
            // mask + count; write masked S^T back into sMt (same quads)
#pragma unroll
            for (int j = 0; j < 4; j++) {
                int c = tx * 4 + j;
                float4 mk = *(const float4*)&sMt[c * 68 + ty * 4];
                cnt[0] += mk.x; cnt[1] += mk.y; cnt[2] += mk.z; cnt[3] += mk.w;
                float4 w;
                w.x = s[0][j] * mk.x;
                w.y = s[1][j] * mk.y;
                w.z = s[2][j] * mk.z;
                w.w = s[3][j] * mk.w;
                *(float4*)&sMt[c * 68 + ty * 4] = w;
            }
            __syncthreads();
            // O += S_masked @ V  (64-deep over keys)
#pragma unroll 8
            for (int c = 0; c < 64; c++) {
                float4 a  = *(const float4*)&sMt[c * 68 + ty * 4];
                float4 bb = *(const float4*)&sV[c * 64 + tx * 4];
                float ar[4] = {a.x, a.y, a.z, a.w};
                float bc[4] = {bb.x, bb.y, bb.z, bb.w};
#pragma unroll
                for (int i = 0; i < 4; i++)
#pragma unroll
                    for (int j = 0; j < 4; j++)
                        po[i][j] = fmaf(ar[i], bc[j], po[i][j]);
            }
        }
        // reduce mask row-count across the 16 lanes sharing ty
#pragma unroll
        for (int off = 8; off >= 1; off >>= 1) {
#pragma unroll
            for (int i = 0; i < 4; i++)
                cnt[i] += __shfl_xor_sync(0xffffffffu, cnt[i], off);
        }
#pragma unroll
        for (int i = 0; i < 4; i++) {
            float inv = 1.0f / cnt[i];
#pragma unroll
            for (int j = 0; j < 4; j++)
                o[i][j] += po[i][j] * inv;
        }
    }
    float* dst = g_acc[t] + (size_t)b * NN * HH;
#pragma unroll
    for (int i = 0; i < 4; i++)
#pragma unroll
        for (int j = 0; j < 4; j++)
            dst[(size_t)(row0 + ty * 4 + i) * HH + tx * 4 + j] = o[i][j];
}

// ============================================================
// Kernel 3: gated Euler update + outputs
// dt = 2*sigmoid(h@Wdt^T + b) - 1 ; hn = h + step*dt*(accin@Wsu^T)
// t=0: accin = [x0 | acc0] (96 wide) ; t=1,2: accin = acc_t (64)
// ============================================================
__global__ void update_kernel(const float* __restrict__ x0,
                              const float* __restrict__ h0,
                              const float* __restrict__ h1,
                              const float* __restrict__ h2,
                              const float* __restrict__ Wsu0,
                              const float* __restrict__ Wsu12,
                              const float* __restrict__ Wdt,
                              const float* __restrict__ bdt,
                              const float* __restrict__ stepp,
                              const float* __restrict__ oscale,
                              float* __restrict__ out2,
                              float* __restrict__ outh0,
                              float* __restrict__ outh1,
                              float* __restrict__ outh2) {
    extern __shared__ float sm[];
    float* sH = sm;               // [64][65]
    float* sW = sm + 64 * 65;     // [64][97]
    float* sA = sW + 64 * 97;     // [64][97]
    int t = blockIdx.y;
    int row0 = blockIdx.x * 64;
    int tid = threadIdx.x, ty = tid >> 4, tx = tid & 15;

    const float* hs = (t == 0) ? h0 : (t == 1 ? h1 : h2);
    float* outh = (t == 0) ? outh0 : (t == 1 ? outh1 : outh2);
    const float* Wd = Wdt + t * HH * HH;

    for (int i = tid; i < 64 * 64; i += 256) {
        int r = i >> 6, c = i & 63;
        sH[r * 65 + c] = hs[(size_t)(row0 + r) * HH + c];
        sW[r * 97 + c] = Wd[i];
    }
    __syncthreads();

    float z[4][4];
#pragma unroll
    for (int j = 0; j < 4; j++) {
        float bj = __ldg(&bdt[t * 64 + tx * 4 + j]);
#pragma unroll
        for (int i = 0; i < 4; i++) z[i][j] = bj;
    }
#pragma unroll 8
    for (int k = 0; k < 64; k++) {
        float a[4], bv[4];
#pragma unroll
        for (int i = 0; i < 4; i++) a[i] = sH[(ty * 4 + i) * 65 + k];
#pragma unroll
        for (int j = 0; j < 4; j++) bv[j] = sW[(tx * 4 + j) * 97 + k];
#pragma unroll
        for (int i = 0; i < 4; i++)
#pragma unroll
            for (int j = 0; j < 4; j++)
                z[i][j] = fmaf(a[i], bv[j], z[i][j]);
    }
    float dtv[4][4];
#pragma unroll
    for (int i = 0; i < 4; i++)
#pragma unroll
        for (int j = 0; j < 4; j++)
            dtv[i][j] = 2.0f / (1.0f + expf(-z[i][j])) - 1.0f;
    __syncthreads();

    int Ksu = (t == 0) ? (INDIM + HH) : HH;   // 96 or 64
    const float* Ws = (t == 0) ? Wsu0 : (Wsu12 + (t - 1) * HH * HH);
    const float* acc = g_acc[t];
    for (int i = tid; i < 64 * Ksu; i += 256) {
        int r = i / Ksu, c = i - r * Ksu;
        sW[r * 97 + c] = Ws[i];
        float av;
        if (t == 0) {
            if (c < INDIM) av = x0[(size_t)(row0 + r) * INDIM + c];
            else           av = acc[(size_t)(row0 + r) * HH + (c - INDIM)];
        } else {
            av = acc[(size_t)(row0 + r) * HH + c];
        }
        sA[r * 97 + c] = av;
    }
    __syncthreads();

    float su[4][4] = {};
#pragma unroll 8
    for (int k = 0; k < Ksu; k++) {
        float a[4], bv[4];
#pragma unroll
        for (int i = 0; i < 4; i++) a[i] = sA[(ty * 4 + i) * 97 + k];
#pragma unroll
        for (int j = 0; j < 4; j++) bv[j] = sW[(tx * 4 + j) * 97 + k];
#pragma unroll
        for (int i = 0; i < 4; i++)
#pragma unroll
            for (int j = 0; j < 4; j++)
                su[i][j] = fmaf(a[i], bv[j], su[i][j]);
    }

    float stepv = *stepp;
    float osc = *oscale;
#pragma unroll
    for (int i = 0; i < 4; i++) {
        int r = row0 + ty * 4 + i;
#pragma unroll
        for (int j = 0; j < 4; j++) {
            int c = tx * 4 + j;
            float hv = sH[(ty * 4 + i) * 65 + c];
            float hn = fmaf(stepv * dtv[i][j], su[i][j], hv);
            outh[(size_t)r * HH + c] = hn;
            if (t == 2 && c < OUTDIM)
                out2[(size_t)r * OUTDIM + c] = osc * hn;
        }
    }
}

// ============================================================
extern "C" void kernel_launch(void* const* d_in, const int* in_sizes, int n_in,
                              void* d_out, int out_size) {
    const float* x0  = (const float*)d_in[0];
    const float* h0  = (const float*)d_in[1];
    const float* h1  = (const float*)d_in[2];
    const float* h2  = (const float*)d_in[3];
    const float* m00 = (const float*)d_in[4];
    const float* m20 = (const float*)d_in[5];
    const float* m01 = (const float*)d_in[6];
    const float* m11 = (const float*)d_in[7];
    const float* m12 = (const float*)d_in[8];
    const float* m22 = (const float*)d_in[9];
    const float* Wq    = (const float*)d_in[10];
    const float* Wk    = (const float*)d_in[11];
    const float* Wsu0  = (const float*)d_in[12];
    const float* Wsu12 = (const float*)d_in[13];
    const float* Wdt   = (const float*)d_in[14];
    const float* bdt   = (const float*)d_in[15];
    const float* stepp = (const float*)d_in[16];
    const float* oscal = (const float*)d_in[17];

    float* out2 = (float*)d_out;
    float* h0n = out2 + (size_t)BB * NN * OUTDIM;
    float* h1n = h0n + (size_t)BB * NN * HH;
    float* h2n = h1n + (size_t)BB * NN * HH;

    const int ATTN_SMEM = (3 * 64 * 68 + 64 * 64) * 4;        // 68608 B
    const int UPD_SMEM  = (64 * 65 + 2 * 64 * 97) * 4;        // 66304 B
    cudaFuncSetAttribute(attn_kernel, cudaFuncAttributeMaxDynamicSharedMemorySize, ATTN_SMEM);
    cudaFuncSetAttribute(update_kernel, cudaFuncAttributeMaxDynamicSharedMemorySize, UPD_SMEM);

    proj_norm_kernel<<<dim3(ROWS / 64, 9), 256>>>(h0, h1, h2, Wq, Wk);
    attn_kernel<<<dim3(NN / 64, 3, BB), 256, ATTN_SMEM>>>(h0, h1, h2,
                                                          m00, m20, m01, m11, m12, m22);
    update_kernel<<<dim3(ROWS / 64, 3), 256, UPD_SMEM>>>(x0, h0, h1, h2,
                                                         Wsu0, Wsu12, Wdt, bdt,
                                                         stepp, oscal,
                                                         out2, h0n, h1n, h2n);
}

// round 3
// speedup vs baseline: 10.5545x; 10.5545x over previous
#include <cuda_runtime.h>
#include <cuda_bf16.h>
#include <cstdint>
#include <math.h>

#define BB 2
#define NN 4096
#define HH 64
#define INDIM 32
#define OUTDIM 8
#define ROWS (BB*NN)

// ---------------- device scratch (static, allocation-free) ----------------
__device__ __align__(16) __nv_bfloat16 g_qnb[3][ROWS*HH];     // normalized queries (bf16)
__device__ __align__(16) __nv_bfloat16 g_knb[6][ROWS*HH];     // normalized keys (bf16)
__device__ __align__(16) __nv_bfloat16 g_v[3][ROWS*HH];       // h values as bf16
__device__ __align__(16) unsigned int  g_mbits[6][NN/32][NN]; // packed masks [e][word][row]
__device__ float g_inv[6][NN];                                // 1/rowcount per edge
__device__ __align__(16) float g_acc[3][ROWS*HH];             // attention result (fp32)

__device__ __forceinline__ uint32_t smem_u32(const void* p) {
    uint32_t a;
    asm("{ .reg .u64 t; cvta.to.shared.u64 t, %1; cvt.u32.u64 %0, t; }" : "=r"(a) : "l"(p));
    return a;
}

// ============================================================
// Kernel 0: mask bit-pack + row-count  (transposed [e][word][row])
// ============================================================
__global__ void mask_pack_kernel(const float* __restrict__ m00, const float* __restrict__ m20,
                                 const float* __restrict__ m01, const float* __restrict__ m11,
                                 const float* __restrict__ m12, const float* __restrict__ m22) {
    const float* tab[6] = {m00, m20, m01, m11, m12, m22};
    int e = blockIdx.y, row = blockIdx.x;
    int wi = threadIdx.x >> 5, lane = threadIdx.x & 31;
    __shared__ int part[4];
    const float* mr = tab[e] + (size_t)row * NN;
    int cnt = 0;
#pragma unroll 4
    for (int it = 0; it < 32; it++) {
        int w = it * 4 + wi;
        float v = mr[w * 32 + lane];
        unsigned bits = __ballot_sync(0xffffffffu, v > 0.5f);
        if (lane == 0) g_mbits[e][w][row] = bits;
        cnt += __popc(bits);
    }
    if (lane == 0) part[wi] = cnt;
    __syncthreads();
    if (threadIdx.x == 0)
        g_inv[e][row] = 1.0f / (float)(part[0] + part[1] + part[2] + part[3]);
}

// ============================================================
// Kernel 1: q/k projections + row L2-normalize -> bf16
// ============================================================
__global__ void proj_norm_kernel(const float* __restrict__ h0,
                                 const float* __restrict__ h1,
                                 const float* __restrict__ h2,
                                 const float* __restrict__ Wq,
                                 const float* __restrict__ Wk) {
    __shared__ float sH[64][65];
    __shared__ float sW[64][65];
    int job = blockIdx.y;
    const float* hs; const float* W; __nv_bfloat16* dst;
    if (job < 3) {
        hs = (job == 0) ? h0 : (job == 1 ? h1 : h2);
        W = Wq + job * HH * HH;
        dst = g_qnb[job];
    } else {
        int e = job - 3;
        int pred = (e == 0 || e == 2) ? 0 : ((e == 3 || e == 4) ? 1 : 2);
        hs = (pred == 0) ? h0 : (pred == 1 ? h1 : h2);
        W = Wk + e * HH * HH;
        dst = g_knb[e];
    }
    int row0 = blockIdx.x * 64;
    int tid = threadIdx.x;
    for (int i = tid; i < 64 * 64; i += 256) {
        int r = i >> 6, c = i & 63;
        sH[r][c] = hs[(size_t)(row0 + r) * HH + c];
        sW[r][c] = W[i];
    }
    __syncthreads();
    int ty = tid >> 4, tx = tid & 15;
    float acc[4][4] = {};
#pragma unroll 8
    for (int k = 0; k < 64; k++) {
        float a[4], bv[4];
#pragma unroll
        for (int i = 0; i < 4; i++) a[i] = sH[ty * 4 + i][k];
#pragma unroll
        for (int j = 0; j < 4; j++) bv[j] = sW[tx * 4 + j][k];
#pragma unroll
        for (int i = 0; i < 4; i++)
#pragma unroll
            for (int j = 0; j < 4; j++)
                acc[i][j] = fmaf(a[i], bv[j], acc[i][j]);
    }
    float ss[4];
#pragma unroll
    for (int i = 0; i < 4; i++)
        ss[i] = acc[i][0]*acc[i][0] + acc[i][1]*acc[i][1] + acc[i][2]*acc[i][2] + acc[i][3]*acc[i][3];
#pragma unroll
    for (int off = 8; off >= 1; off >>= 1)
#pragma unroll
        for (int i = 0; i < 4; i++)
            ss[i] += __shfl_xor_sync(0xffffffffu, ss[i], off);
#pragma unroll
    for (int i = 0; i < 4; i++) {
        float inv = rsqrtf(ss[i]);
#pragma unroll
        for (int j = 0; j < 4; j++)
            dst[(size_t)(row0 + ty * 4 + i) * HH + tx * 4 + j] = __float2bfloat16(acc[i][j] * inv);
    }
}

// ============================================================
// Kernel 2: convert h -> bf16 values
// ============================================================
__global__ void conv_v_kernel(const float* __restrict__ h0,
                              const float* __restrict__ h1,
                              const float* __restrict__ h2) {
    const float* src = (blockIdx.y == 0) ? h0 : (blockIdx.y == 1 ? h1 : h2);
    __nv_bfloat16* dst = g_v[blockIdx.y];
    int idx = blockIdx.x * 256 + threadIdx.x;
    float4 v = ((const float4*)src)[idx];
    ((__nv_bfloat162*)dst)[idx * 2]     = __floats2bfloat162_rn(v.x, v.y);
    ((__nv_bfloat162*)dst)[idx * 2 + 1] = __floats2bfloat162_rn(v.z, v.w);
}

// ============================================================
// Kernel 3: masked cosine attention via mma.sync m16n8k16 bf16
// CTA = 4 warps = 64 query rows, one (t,b). BN=64 keys/tile, D=64.
// P (masked, scaled S) stays in registers: C-frag layout == A-frag layout.
// ============================================================
#define LDS_PAD 72   // smem row stride in halves (64 + 8)

#define LDSM_X4(r0,r1,r2,r3,addr) \
    asm volatile("ldmatrix.sync.aligned.m8n8.x4.shared.b16 {%0,%1,%2,%3}, [%4];" \
        : "=r"(r0), "=r"(r1), "=r"(r2), "=r"(r3) : "r"(addr))
#define LDSM_X4_T(r0,r1,r2,r3,addr) \
    asm volatile("ldmatrix.sync.aligned.m8n8.x4.trans.shared.b16 {%0,%1,%2,%3}, [%4];" \
        : "=r"(r0), "=r"(r1), "=r"(r2), "=r"(r3) : "r"(addr))
#define MMA16816(c, a, b0, b1) \
    asm volatile("mma.sync.aligned.m16n8k16.row.col.f32.bf16.bf16.f32 " \
        "{%0,%1,%2,%3}, {%4,%5,%6,%7}, {%8,%9}, {%0,%1,%2,%3};" \
        : "+f"((c)[0]), "+f"((c)[1]), "+f"((c)[2]), "+f"((c)[3]) \
        : "r"((a)[0]), "r"((a)[1]), "r"((a)[2]), "r"((a)[3]), "r"(b0), "r"(b1))

__global__ void __launch_bounds__(128) attn_mma_kernel() {
    __shared__ __nv_bfloat16 sQ[64 * LDS_PAD];
    __shared__ __nv_bfloat16 sK[64 * LDS_PAD];
    __shared__ __nv_bfloat16 sV[64 * LDS_PAD];

    int tid = threadIdx.x, warp = tid >> 5, lane = tid & 31;
    int g = lane >> 2, tig = lane & 3;
    int t = blockIdx.y, b = blockIdx.z;
    int row0 = blockIdx.x * 64;

    uint32_t sQb = smem_u32(sQ), sKb = smem_u32(sK), sVb = smem_u32(sV);

    // ---- stage Q tile (64 rows x 64 bf16) ----
    const __nv_bfloat16* qg = g_qnb[t] + ((size_t)b * NN + row0) * HH;
#pragma unroll
    for (int i = 0; i < 4; i++) {
        int idx = i * 128 + tid;            // 512 uint4 chunks
        int r = idx >> 3, c = idx & 7;
        *(uint4*)&sQ[r * LDS_PAD + c * 8] = *(const uint4*)&qg[r * HH + c * 8];
    }
    __syncthreads();

    // ---- Q A-fragments: qa[kc][4], kc = 16-wide k-chunk of d ----
    // x4 lane map: row = lane&15, col = kc*16 + 8*(lane>>4)
    uint32_t qa[4][4];
    {
        int qrow = warp * 16 + (lane & 15);
        int qcol = (lane >> 4) << 3;
#pragma unroll
        for (int kc = 0; kc < 4; kc++) {
            uint32_t addr = sQb + (uint32_t)(qrow * LDS_PAD + kc * 16 + qcol) * 2;
            LDSM_X4(qa[kc][0], qa[kc][1], qa[kc][2], qa[kc][3], addr);
        }
    }

    int rowA = row0 + warp * 16 + g;
    int rowB = rowA + 8;

    float o[8][4] = {};                 // O accum: 8 d-ntiles x 4
    const int vpred[6] = {0, 2, 0, 1, 1, 2};

    for (int ee = 0; ee < 2; ee++) {
        int e = 2 * t + ee;
        const __nv_bfloat16* kg0 = g_knb[e] + (size_t)b * NN * HH;
        const __nv_bfloat16* vg0 = g_v[vpred[e]] + (size_t)b * NN * HH;
        float invA = g_inv[e][rowA];
        float invB = g_inv[e][rowB];

        for (int kt = 0; kt < NN / 64; kt++) {
            __syncthreads();   // prev tile's readers done
            const __nv_bfloat16* kg = kg0 + (size_t)kt * 64 * HH;
            const __nv_bfloat16* vg = vg0 + (size_t)kt * 64 * HH;
#pragma unroll
            for (int i = 0; i < 4; i++) {
                int idx = i * 128 + tid;
                int r = idx >> 3, c = idx & 7;
                *(uint4*)&sK[r * LDS_PAD + c * 8] = *(const uint4*)&kg[r * HH + c * 8];
                *(uint4*)&sV[r * LDS_PAD + c * 8] = *(const uint4*)&vg[r * HH + c * 8];
            }
            // mask words: 2 per row for this 64-key tile
            uint32_t mA0 = g_mbits[e][kt * 2][rowA],     mA1 = g_mbits[e][kt * 2 + 1][rowA];
            uint32_t mB0 = g_mbits[e][kt * 2][rowB],     mB1 = g_mbits[e][kt * 2 + 1][rowB];
            __syncthreads();

            // ---- S = Q @ K^T  (64 rows x 64 keys), s[j] = 8-key ntile ----
            float s[8][4] = {};
            {
                // B-frag lane map: row = 16*jp + 8*(lane>>4) + (lane&7),
                //                  col = kc*16 + 8*((lane>>3)&1)
                int krow_off = ((lane >> 4) << 3) + (lane & 7);
                int kcol_off = ((lane >> 3) & 1) << 3;
#pragma unroll
                for (int kc = 0; kc < 4; kc++) {
#pragma unroll
                    for (int jp = 0; jp < 4; jp++) {
                        uint32_t b0, b1, b2, b3;
                        uint32_t addr = sKb + (uint32_t)((16 * jp + krow_off) * LDS_PAD
                                                          + kc * 16 + kcol_off) * 2;
                        LDSM_X4(b0, b1, b2, b3, addr);
                        MMA16816(s[2 * jp],     qa[kc], b0, b1);
                        MMA16816(s[2 * jp + 1], qa[kc], b2, b3);
                    }
                }
            }

            // ---- register epilogue: mask + 1/cnt + bf16 pack -> A-frags pa ----
            uint32_t pa[4][4];
#pragma unroll
            for (int j = 0; j < 8; j++) {
                uint32_t wA = (j < 4) ? mA0 : mA1;
                uint32_t wB = (j < 4) ? mB0 : mB1;
                int bit = (j * 8 + 2 * tig) & 31;
                float f0 = ((wA >> bit) & 1u)       ? s[j][0] * invA : 0.0f;
                float f1 = ((wA >> (bit + 1)) & 1u) ? s[j][1] * invA : 0.0f;
                float f2 = ((wB >> bit) & 1u)       ? s[j][2] * invB : 0.0f;
                float f3 = ((wB >> (bit + 1)) & 1u) ? s[j][3] * invB : 0.0f;
                uint32_t p01, p23;
                asm("cvt.rn.bf16x2.f32 %0, %1, %2;" : "=r"(p01) : "f"(f1), "f"(f0));
                asm("cvt.rn.bf16x2.f32 %0, %1, %2;" : "=r"(p23) : "f"(f3), "f"(f2));
                pa[j >> 1][(j & 1) * 2]     = p01;
                pa[j >> 1][(j & 1) * 2 + 1] = p23;
            }

            // ---- O += P @ V  (keys inner, 64 deep; 8 d-ntiles) ----
            {
                // trans B-frag lane map: row = 32*kcp + lane, col = 8*nt
                int vrow = lane;
#pragma unroll
                for (int kcp = 0; kcp < 2; kcp++) {
#pragma unroll
                    for (int nt = 0; nt < 8; nt++) {
                        uint32_t b0, b1, b2, b3;
                        uint32_t addr = sVb + (uint32_t)((32 * kcp + vrow) * LDS_PAD
                                                          + nt * 8) * 2;
                        LDSM_X4_T(b0, b1, b2, b3, addr);
                        MMA16816(o[nt], pa[2 * kcp],     b0, b1);
                        MMA16816(o[nt], pa[2 * kcp + 1], b2, b3);
                    }
                }
            }
        }
    }

    // ---- write O (fp32) ----
    float* dst = g_acc[t] + (size_t)b * NN * HH;
#pragma unroll
    for (int nt = 0; nt < 8; nt++) {
        int col = nt * 8 + 2 * tig;
        *(float2*)&dst[(size_t)rowA * HH + col] = make_float2(o[nt][0], o[nt][1]);
        *(float2*)&dst[(size_t)rowB * HH + col] = make_float2(o[nt][2], o[nt][3]);
    }
}

// ============================================================
// Kernel 4: gated Euler update + outputs (fp32)
// ============================================================
__global__ void update_kernel(const float* __restrict__ x0,
                              const float* __restrict__ h0,
                              const float* __restrict__ h1,
                              const float* __restrict__ h2,
                              const float* __restrict__ Wsu0,
                              const float* __restrict__ Wsu12,
                              const float* __restrict__ Wdt,
                              const float* __restrict__ bdt,
                              const float* __restrict__ stepp,
                              const float* __restrict__ oscale,
                              float* __restrict__ out2,
                              float* __restrict__ outh0,
                              float* __restrict__ outh1,
                              float* __restrict__ outh2) {
    extern __shared__ float sm[];
    float* sH = sm;               // [64][65]
    float* sW = sm + 64 * 65;     // [64][97]
    float* sA = sW + 64 * 97;     // [64][97]
    int t = blockIdx.y;
    int row0 = blockIdx.x * 64;
    int tid = threadIdx.x, ty = tid >> 4, tx = tid & 15;

    const float* hs = (t == 0) ? h0 : (t == 1 ? h1 : h2);
    float* outh = (t == 0) ? outh0 : (t == 1 ? outh1 : outh2);
    const float* Wd = Wdt + t * HH * HH;

    for (int i = tid; i < 64 * 64; i += 256) {
        int r = i >> 6, c = i & 63;
        sH[r * 65 + c] = hs[(size_t)(row0 + r) * HH + c];
        sW[r * 97 + c] = Wd[i];
    }
    __syncthreads();

    float z[4][4];
#pragma unroll
    for (int j = 0; j < 4; j++) {
        float bj = __ldg(&bdt[t * 64 + tx * 4 + j]);
#pragma unroll
        for (int i = 0; i < 4; i++) z[i][j] = bj;
    }
#pragma unroll 8
    for (int k = 0; k < 64; k++) {
        float a[4], bv[4];
#pragma unroll
        for (int i = 0; i < 4; i++) a[i] = sH[(ty * 4 + i) * 65 + k];
#pragma unroll
        for (int j = 0; j < 4; j++) bv[j] = sW[(tx * 4 + j) * 97 + k];
#pragma unroll
        for (int i = 0; i < 4; i++)
#pragma unroll
            for (int j = 0; j < 4; j++)
                z[i][j] = fmaf(a[i], bv[j], z[i][j]);
    }
    float dtv[4][4];
#pragma unroll
    for (int i = 0; i < 4; i++)
#pragma unroll
        for (int j = 0; j < 4; j++)
            dtv[i][j] = 2.0f / (1.0f + expf(-z[i][j])) - 1.0f;
    __syncthreads();

    int Ksu = (t == 0) ? (INDIM + HH) : HH;
    const float* Ws = (t == 0) ? Wsu0 : (Wsu12 + (t - 1) * HH * HH);
    const float* acc = g_acc[t];
    for (int i = tid; i < 64 * Ksu; i += 256) {
        int r = i / Ksu, c = i - r * Ksu;
        sW[r * 97 + c] = Ws[i];
        float av;
        if (t == 0) {
            if (c < INDIM) av = x0[(size_t)(row0 + r) * INDIM + c];
            else           av = acc[(size_t)(row0 + r) * HH + (c - INDIM)];
        } else {
            av = acc[(size_t)(row0 + r) * HH + c];
        }
        sA[r * 97 + c] = av;
    }
    __syncthreads();

    float su[4][4] = {};
#pragma unroll 8
    for (int k = 0; k < Ksu; k++) {
        float a[4], bv[4];
#pragma unroll
        for (int i = 0; i < 4; i++) a[i] = sA[(ty * 4 + i) * 97 + k];
#pragma unroll
        for (int j = 0; j < 4; j++) bv[j] = sW[(tx * 4 + j) * 97 + k];
#pragma unroll
        for (int i = 0; i < 4; i++)
#pragma unroll
            for (int j = 0; j < 4; j++)
                su[i][j] = fmaf(a[i], bv[j], su[i][j]);
    }

    float stepv = *stepp;
    float osc = *oscale;
#pragma unroll
    for (int i = 0; i < 4; i++) {
        int r = row0 + ty * 4 + i;
#pragma unroll
        for (int j = 0; j < 4; j++) {
            int c = tx * 4 + j;
            float hv = sH[(ty * 4 + i) * 65 + c];
            float hn = fmaf(stepv * dtv[i][j], su[i][j], hv);
            outh[(size_t)r * HH + c] = hn;
            if (t == 2 && c < OUTDIM)
                out2[(size_t)r * OUTDIM + c] = osc * hn;
        }
    }
}

// ============================================================
extern "C" void kernel_launch(void* const* d_in, const int* in_sizes, int n_in,
                              void* d_out, int out_size) {
    const float* x0  = (const float*)d_in[0];
    const float* h0  = (const float*)d_in[1];
    const float* h1  = (const float*)d_in[2];
    const float* h2  = (const float*)d_in[3];
    const float* m00 = (const float*)d_in[4];
    const float* m20 = (const float*)d_in[5];
    const float* m01 = (const float*)d_in[6];
    const float* m11 = (const float*)d_in[7];
    const float* m12 = (const float*)d_in[8];
    const float* m22 = (const float*)d_in[9];
    const float* Wq    = (const float*)d_in[10];
    const float* Wk    = (const float*)d_in[11];
    const float* Wsu0  = (const float*)d_in[12];
    const float* Wsu12 = (const float*)d_in[13];
    const float* Wdt   = (const float*)d_in[14];
    const float* bdt   = (const float*)d_in[15];
    const float* stepp = (const float*)d_in[16];
    const float* oscal = (const float*)d_in[17];

    float* out2 = (float*)d_out;
    float* h0n = out2 + (size_t)BB * NN * OUTDIM;
    float* h1n = h0n + (size_t)BB * NN * HH;
    float* h2n = h1n + (size_t)BB * NN * HH;

    const int UPD_SMEM = (64 * 65 + 2 * 64 * 97) * 4;
    cudaFuncSetAttribute(update_kernel, cudaFuncAttributeMaxDynamicSharedMemorySize, UPD_SMEM);

    mask_pack_kernel<<<dim3(NN, 6), 128>>>(m00, m20, m01, m11, m12, m22);
    proj_norm_kernel<<<dim3(ROWS / 64, 9), 256>>>(h0, h1, h2, Wq, Wk);
    conv_v_kernel<<<dim3(ROWS * HH / 4 / 256, 3), 256>>>(h0, h1, h2);
    attn_mma_kernel<<<dim3(NN / 64, 3, BB), 128>>>();
    update_kernel<<<dim3(ROWS / 64, 3), 256, UPD_SMEM>>>(x0, h0, h1, h2,
                                                         Wsu0, Wsu12, Wdt, bdt,
                                                         stepp, oscal,
                                                         out2, h0n, h1n, h2n);
}

// round 4
// speedup vs baseline: 11.1129x; 1.0529x over previous
#include <cuda_runtime.h>
#include <cuda_bf16.h>
#include <cstdint>
#include <math.h>

#define BB 2
#define NN 4096
#define HH 64
#define INDIM 32
#define OUTDIM 8
#define ROWS (BB*NN)
#define NSPLIT 4

// ---------------- device scratch (static, allocation-free) ----------------
__device__ __align__(16) __nv_bfloat16 g_qnb[3][ROWS*HH];     // normalized queries (bf16)
__device__ __align__(16) __nv_bfloat16 g_knb[6][ROWS*HH];     // normalized keys (bf16)
__device__ __align__(16) __nv_bfloat16 g_v[3][ROWS*HH];       // h values as bf16
__device__ __align__(16) unsigned int  g_mbits[6][NN/32][NN]; // packed masks [e][word][row]
__device__ float g_inv[6][NN];                                // 1/rowcount per edge
__device__ __align__(16) float g_acc[3][ROWS*HH];             // attention result (fp32)

__device__ __forceinline__ uint32_t smem_u32(const void* p) {
    uint32_t a;
    asm("{ .reg .u64 t; cvta.to.shared.u64 t, %1; cvt.u32.u64 %0, t; }" : "=r"(a) : "l"(p));
    return a;
}

// ============================================================
// Kernel 0: mask bit-pack + row-count. One row per warp.
// ============================================================
__global__ void mask_pack_kernel(const float* __restrict__ m00, const float* __restrict__ m20,
                                 const float* __restrict__ m01, const float* __restrict__ m11,
                                 const float* __restrict__ m12, const float* __restrict__ m22) {
    const float* tab[6] = {m00, m20, m01, m11, m12, m22};
    int e = blockIdx.y;
    int wi = threadIdx.x >> 5, lane = threadIdx.x & 31;
    int row = blockIdx.x * 4 + wi;
    const float* mr = tab[e] + (size_t)row * NN;
    int cnt = 0;
#pragma unroll 8
    for (int w = 0; w < NN / 32; w++) {
        float v = mr[w * 32 + lane];
        unsigned bits = __ballot_sync(0xffffffffu, v > 0.5f);
        if (lane == 0) g_mbits[e][w][row] = bits;
        cnt += __popc(bits);
    }
    if (lane == 0) g_inv[e][row] = 1.0f / (float)cnt;
}

// ============================================================
// Kernel 1: q/k projections + row L2-normalize -> bf16
// ============================================================
__global__ void proj_norm_kernel(const float* __restrict__ h0,
                                 const float* __restrict__ h1,
                                 const float* __restrict__ h2,
                                 const float* __restrict__ Wq,
                                 const float* __restrict__ Wk) {
    __shared__ float sH[64][65];
    __shared__ float sW[64][65];
    int job = blockIdx.y;
    const float* hs; const float* W; __nv_bfloat16* dst;
    if (job < 3) {
        hs = (job == 0) ? h0 : (job == 1 ? h1 : h2);
        W = Wq + job * HH * HH;
        dst = g_qnb[job];
    } else {
        int e = job - 3;
        int pred = (e == 0 || e == 2) ? 0 : ((e == 3 || e == 4) ? 1 : 2);
        hs = (pred == 0) ? h0 : (pred == 1 ? h1 : h2);
        W = Wk + e * HH * HH;
        dst = g_knb[e];
    }
    int row0 = blockIdx.x * 64;
    int tid = threadIdx.x;
    for (int i = tid; i < 64 * 64; i += 256) {
        int r = i >> 6, c = i & 63;
        sH[r][c] = hs[(size_t)(row0 + r) * HH + c];
        sW[r][c] = W[i];
    }
    __syncthreads();
    int ty = tid >> 4, tx = tid & 15;
    float acc[4][4] = {};
#pragma unroll 8
    for (int k = 0; k < 64; k++) {
        float a[4], bv[4];
#pragma unroll
        for (int i = 0; i < 4; i++) a[i] = sH[ty * 4 + i][k];
#pragma unroll
        for (int j = 0; j < 4; j++) bv[j] = sW[tx * 4 + j][k];
#pragma unroll
        for (int i = 0; i < 4; i++)
#pragma unroll
            for (int j = 0; j < 4; j++)
                acc[i][j] = fmaf(a[i], bv[j], acc[i][j]);
    }
    float ss[4];
#pragma unroll
    for (int i = 0; i < 4; i++)
        ss[i] = acc[i][0]*acc[i][0] + acc[i][1]*acc[i][1] + acc[i][2]*acc[i][2] + acc[i][3]*acc[i][3];
#pragma unroll
    for (int off = 8; off >= 1; off >>= 1)
#pragma unroll
        for (int i = 0; i < 4; i++)
            ss[i] += __shfl_xor_sync(0xffffffffu, ss[i], off);
#pragma unroll
    for (int i = 0; i < 4; i++) {
        float inv = rsqrtf(ss[i]);
#pragma unroll
        for (int j = 0; j < 4; j++)
            dst[(size_t)(row0 + ty * 4 + i) * HH + tx * 4 + j] = __float2bfloat16(acc[i][j] * inv);
    }
}

// ============================================================
// Kernel 2: convert h -> bf16 values; also zero g_acc for split-K atomics
// ============================================================
__global__ void conv_v_kernel(const float* __restrict__ h0,
                              const float* __restrict__ h1,
                              const float* __restrict__ h2) {
    const float* src = (blockIdx.y == 0) ? h0 : (blockIdx.y == 1 ? h1 : h2);
    __nv_bfloat16* dst = g_v[blockIdx.y];
    int idx = blockIdx.x * 256 + threadIdx.x;
    float4 v = ((const float4*)src)[idx];
    ((__nv_bfloat162*)dst)[idx * 2]     = __floats2bfloat162_rn(v.x, v.y);
    ((__nv_bfloat162*)dst)[idx * 2 + 1] = __floats2bfloat162_rn(v.z, v.w);
    ((float4*)g_acc[blockIdx.y])[idx] = make_float4(0.f, 0.f, 0.f, 0.f);
}

// ============================================================
// Kernel 3: masked cosine attention via mma.sync m16n8k16 bf16
// CTA = 4 warps = 128 query rows (32 rows/warp, 2 row-blocks), one
// (t,b,split). Each split handles 16 of 64 key tiles per edge; partial O
// accumulated into g_acc via atomicAdd.
// ============================================================
#define LDS_PAD 72   // smem row stride in halves (64 + 8)

#define LDSM_X4(r0,r1,r2,r3,addr) \
    asm volatile("ldmatrix.sync.aligned.m8n8.x4.shared.b16 {%0,%1,%2,%3}, [%4];" \
        : "=r"(r0), "=r"(r1), "=r"(r2), "=r"(r3) : "r"(addr))
#define LDSM_X4_T(r0,r1,r2,r3,addr) \
    asm volatile("ldmatrix.sync.aligned.m8n8.x4.trans.shared.b16 {%0,%1,%2,%3}, [%4];" \
        : "=r"(r0), "=r"(r1), "=r"(r2), "=r"(r3) : "r"(addr))
#define MMA16816(c, a, b0, b1) \
    asm volatile("mma.sync.aligned.m16n8k16.row.col.f32.bf16.bf16.f32 " \
        "{%0,%1,%2,%3}, {%4,%5,%6,%7}, {%8,%9}, {%0,%1,%2,%3};" \
        : "+f"((c)[0]), "+f"((c)[1]), "+f"((c)[2]), "+f"((c)[3]) \
        : "r"((a)[0]), "r"((a)[1]), "r"((a)[2]), "r"((a)[3]), "r"(b0), "r"(b1))

__global__ void __launch_bounds__(128, 1) attn_mma_kernel() {
    __shared__ __nv_bfloat16 sQ[128 * LDS_PAD];
    __shared__ __nv_bfloat16 sK[64 * LDS_PAD];
    __shared__ __nv_bfloat16 sV[64 * LDS_PAD];

    int tid = threadIdx.x, warp = tid >> 5, lane = tid & 31;
    int g = lane >> 2, tig = lane & 3;
    int t = blockIdx.z >> 1, b = blockIdx.z & 1;
    int split = blockIdx.y;
    int row0 = blockIdx.x * 128;

    uint32_t sQb = smem_u32(sQ), sKb = smem_u32(sK), sVb = smem_u32(sV);

    // ---- stage Q tile (128 rows x 64 bf16) ----
    const __nv_bfloat16* qg = g_qnb[t] + ((size_t)b * NN + row0) * HH;
#pragma unroll
    for (int i = 0; i < 8; i++) {
        int idx = i * 128 + tid;            // 1024 uint4 chunks
        int r = idx >> 3, c = idx & 7;
        *(uint4*)&sQ[r * LDS_PAD + c * 8] = *(const uint4*)&qg[r * HH + c * 8];
    }
    __syncthreads();

    // ---- Q A-fragments per row-block: qa[rb][kc][4] ----
    uint32_t qa[2][4][4];
    {
        int qcol = (lane >> 4) << 3;
#pragma unroll
        for (int rb = 0; rb < 2; rb++) {
            int qrow = warp * 32 + rb * 16 + (lane & 15);
#pragma unroll
            for (int kc = 0; kc < 4; kc++) {
                uint32_t addr = sQb + (uint32_t)(qrow * LDS_PAD + kc * 16 + qcol) * 2;
                LDSM_X4(qa[rb][kc][0], qa[rb][kc][1], qa[rb][kc][2], qa[rb][kc][3], addr);
            }
        }
    }

    int rowA[2], rowB[2];
#pragma unroll
    for (int rb = 0; rb < 2; rb++) {
        rowA[rb] = row0 + warp * 32 + rb * 16 + g;
        rowB[rb] = rowA[rb] + 8;
    }

    float o[2][8][4] = {};
    const int vpred[6] = {0, 2, 0, 1, 1, 2};

    for (int ee = 0; ee < 2; ee++) {
        int e = 2 * t + ee;
        const __nv_bfloat16* kg0 = g_knb[e] + (size_t)b * NN * HH;
        const __nv_bfloat16* vg0 = g_v[vpred[e]] + (size_t)b * NN * HH;
        float invA[2], invB[2];
#pragma unroll
        for (int rb = 0; rb < 2; rb++) {
            invA[rb] = g_inv[e][rowA[rb]];
            invB[rb] = g_inv[e][rowB[rb]];
        }

        for (int kt = split * 16; kt < split * 16 + 16; kt++) {
            __syncthreads();   // prev tile's readers done
            const __nv_bfloat16* kg = kg0 + (size_t)kt * 64 * HH;
            const __nv_bfloat16* vg = vg0 + (size_t)kt * 64 * HH;
#pragma unroll
            for (int i = 0; i < 4; i++) {
                int idx = i * 128 + tid;
                int r = idx >> 3, c = idx & 7;
                *(uint4*)&sK[r * LDS_PAD + c * 8] = *(const uint4*)&kg[r * HH + c * 8];
                *(uint4*)&sV[r * LDS_PAD + c * 8] = *(const uint4*)&vg[r * HH + c * 8];
            }
            uint32_t mA[2][2], mB[2][2];
#pragma unroll
            for (int rb = 0; rb < 2; rb++) {
#pragma unroll
                for (int w = 0; w < 2; w++) {
                    mA[rb][w] = g_mbits[e][kt * 2 + w][rowA[rb]];
                    mB[rb][w] = g_mbits[e][kt * 2 + w][rowB[rb]];
                }
            }
            __syncthreads();

            // ---- S = Q @ K^T : K B-frag loaded once, feeds both row-blocks ----
            float s[2][8][4] = {};
            {
                int krow_off = ((lane >> 4) << 3) + (lane & 7);
                int kcol_off = ((lane >> 3) & 1) << 3;
#pragma unroll
                for (int kc = 0; kc < 4; kc++) {
#pragma unroll
                    for (int jp = 0; jp < 4; jp++) {
                        uint32_t b0, b1, b2, b3;
                        uint32_t addr = sKb + (uint32_t)((16 * jp + krow_off) * LDS_PAD
                                                          + kc * 16 + kcol_off) * 2;
                        LDSM_X4(b0, b1, b2, b3, addr);
#pragma unroll
                        for (int rb = 0; rb < 2; rb++) {
                            MMA16816(s[rb][2 * jp],     qa[rb][kc], b0, b1);
                            MMA16816(s[rb][2 * jp + 1], qa[rb][kc], b2, b3);
                        }
                    }
                }
            }

            // ---- register epilogue: mask + 1/cnt + bf16 pack -> A-frags pa ----
            uint32_t pa[2][4][4];
#pragma unroll
            for (int rb = 0; rb < 2; rb++) {
#pragma unroll
                for (int j = 0; j < 8; j++) {
                    uint32_t wA = mA[rb][j >> 2];
                    uint32_t wB = mB[rb][j >> 2];
                    int bit = (j * 8 + 2 * tig) & 31;
                    float f0 = ((wA >> bit) & 1u)       ? s[rb][j][0] * invA[rb] : 0.0f;
                    float f1 = ((wA >> (bit + 1)) & 1u) ? s[rb][j][1] * invA[rb] : 0.0f;
                    float f2 = ((wB >> bit) & 1u)       ? s[rb][j][2] * invB[rb] : 0.0f;
                    float f3 = ((wB >> (bit + 1)) & 1u) ? s[rb][j][3] * invB[rb] : 0.0f;
                    uint32_t p01, p23;
                    asm("cvt.rn.bf16x2.f32 %0, %1, %2;" : "=r"(p01) : "f"(f1), "f"(f0));
                    asm("cvt.rn.bf16x2.f32 %0, %1, %2;" : "=r"(p23) : "f"(f3), "f"(f2));
                    pa[rb][j >> 1][(j & 1) * 2]     = p01;
                    pa[rb][j >> 1][(j & 1) * 2 + 1] = p23;
                }
            }

            // ---- O += P @ V : V B-frag loaded once, feeds both row-blocks ----
            {
#pragma unroll
                for (int kcp = 0; kcp < 2; kcp++) {
#pragma unroll
                    for (int nt = 0; nt < 8; nt++) {
                        uint32_t b0, b1, b2, b3;
                        uint32_t addr = sVb + (uint32_t)((32 * kcp + lane) * LDS_PAD
                                                          + nt * 8) * 2;
                        LDSM_X4_T(b0, b1, b2, b3, addr);
#pragma unroll
                        for (int rb = 0; rb < 2; rb++) {
                            MMA16816(o[rb][nt], pa[rb][2 * kcp],     b0, b1);
                            MMA16816(o[rb][nt], pa[rb][2 * kcp + 1], b2, b3);
                        }
                    }
                }
            }
        }
    }

    // ---- accumulate partial O into g_acc (fp32 atomics, RED path) ----
    float* dst = g_acc[t] + (size_t)b * NN * HH;
#pragma unroll
    for (int rb = 0; rb < 2; rb++) {
#pragma unroll
        for (int nt = 0; nt < 8; nt++) {
            int col = nt * 8 + 2 * tig;
            atomicAdd(&dst[(size_t)rowA[rb] * HH + col],     o[rb][nt][0]);
            atomicAdd(&dst[(size_t)rowA[rb] * HH + col + 1], o[rb][nt][1]);
            atomicAdd(&dst[(size_t)rowB[rb] * HH + col],     o[rb][nt][2]);
            atomicAdd(&dst[(size_t)rowB[rb] * HH + col + 1], o[rb][nt][3]);
        }
    }
}

// ============================================================
// Kernel 4: gated Euler update + outputs (fp32)
// ============================================================
__global__ void update_kernel(const float* __restrict__ x0,
                              const float* __restrict__ h0,
                              const float* __restrict__ h1,
                              const float* __restrict__ h2,
                              const float* __restrict__ Wsu0,
                              const float* __restrict__ Wsu12,
                              const float* __restrict__ Wdt,
                              const float* __restrict__ bdt,
                              const float* __restrict__ stepp,
                              const float* __restrict__ oscale,
                              float* __restrict__ out2,
                              float* __restrict__ outh0,
                              float* __restrict__ outh1,
                              float* __restrict__ outh2) {
    extern __shared__ float sm[];
    float* sH = sm;               // [64][65]
    float* sW = sm + 64 * 65;     // [64][97]
    float* sA = sW + 64 * 97;     // [64][97]
    int t = blockIdx.y;
    int row0 = blockIdx.x * 64;
    int tid = threadIdx.x, ty = tid >> 4, tx = tid & 15;

    const float* hs = (t == 0) ? h0 : (t == 1 ? h1 : h2);
    float* outh = (t == 0) ? outh0 : (t == 1 ? outh1 : outh2);
    const float* Wd = Wdt + t * HH * HH;

    for (int i = tid; i < 64 * 64; i += 256) {
        int r = i >> 6, c = i & 63;
        sH[r * 65 + c] = hs[(size_t)(row0 + r) * HH + c];
        sW[r * 97 + c] = Wd[i];
    }
    __syncthreads();

    float z[4][4];
#pragma unroll
    for (int j = 0; j < 4; j++) {
        float bj = __ldg(&bdt[t * 64 + tx * 4 + j]);
#pragma unroll
        for (int i = 0; i < 4; i++) z[i][j] = bj;
    }
#pragma unroll 8
    for (int k = 0; k < 64; k++) {
        float a[4], bv[4];
#pragma unroll
        for (int i = 0; i < 4; i++) a[i] = sH[(ty * 4 + i) * 65 + k];
#pragma unroll
        for (int j = 0; j < 4; j++) bv[j] = sW[(tx * 4 + j) * 97 + k];
#pragma unroll
        for (int i = 0; i < 4; i++)
#pragma unroll
            for (int j = 0; j < 4; j++)
                z[i][j] = fmaf(a[i], bv[j], z[i][j]);
    }
    float dtv[4][4];
#pragma unroll
    for (int i = 0; i < 4; i++)
#pragma unroll
        for (int j = 0; j < 4; j++)
            dtv[i][j] = 2.0f / (1.0f + expf(-z[i][j])) - 1.0f;
    __syncthreads();

    int Ksu = (t == 0) ? (INDIM + HH) : HH;
    const float* Ws = (t == 0) ? Wsu0 : (Wsu12 + (t - 1) * HH * HH);
    const float* acc = g_acc[t];
    for (int i = tid; i < 64 * Ksu; i += 256) {
        int r = i / Ksu, c = i - r * Ksu;
        sW[r * 97 + c] = Ws[i];
        float av;
        if (t == 0) {
            if (c < INDIM) av = x0[(size_t)(row0 + r) * INDIM + c];
            else           av = acc[(size_t)(row0 + r) * HH + (c - INDIM)];
        } else {
            av = acc[(size_t)(row0 + r) * HH + c];
        }
        sA[r * 97 + c] = av;
    }
    __syncthreads();

    float su[4][4] = {};
#pragma unroll 8
    for (int k = 0; k < Ksu; k++) {
        float a[4], bv[4];
#pragma unroll
        for (int i = 0; i < 4; i++) a[i] = sA[(ty * 4 + i) * 97 + k];
#pragma unroll
        for (int j = 0; j < 4; j++) bv[j] = sW[(tx * 4 + j) * 97 + k];
#pragma unroll
        for (int i = 0; i < 4; i++)
#pragma unroll
            for (int j = 0; j < 4; j++)
                su[i][j] = fmaf(a[i], bv[j], su[i][j]);
    }

    float stepv = *stepp;
    float osc = *oscale;
#pragma unroll
    for (int i = 0; i < 4; i++) {
        int r = row0 + ty * 4 + i;
#pragma unroll
        for (int j = 0; j < 4; j++) {
            int c = tx * 4 + j;
            float hv = sH[(ty * 4 + i) * 65 + c];
            float hn = fmaf(stepv * dtv[i][j], su[i][j], hv);
            outh[(size_t)r * HH + c] = hn;
            if (t == 2 && c < OUTDIM)
                out2[(size_t)r * OUTDIM + c] = osc * hn;
        }
    }
}

// ============================================================
extern "C" void kernel_launch(void* const* d_in, const int* in_sizes, int n_in,
                              void* d_out, int out_size) {
    const float* x0  = (const float*)d_in[0];
    const float* h0  = (const float*)d_in[1];
    const float* h1  = (const float*)d_in[2];
    const float* h2  = (const float*)d_in[3];
    const float* m00 = (const float*)d_in[4];
    const float* m20 = (const float*)d_in[5];
    const float* m01 = (const float*)d_in[6];
    const float* m11 = (const float*)d_in[7];
    const float* m12 = (const float*)d_in[8];
    const float* m22 = (const float*)d_in[9];
    const float* Wq    = (const float*)d_in[10];
    const float* Wk    = (const float*)d_in[11];
    const float* Wsu0  = (const float*)d_in[12];
    const float* Wsu12 = (const float*)d_in[13];
    const float* Wdt   = (const float*)d_in[14];
    const float* bdt   = (const float*)d_in[15];
    const float* stepp = (const float*)d_in[16];
    const float* oscal = (const float*)d_in[17];

    float* out2 = (float*)d_out;
    float* h0n = out2 + (size_t)BB * NN * OUTDIM;
    float* h1n = h0n + (size_t)BB * NN * HH;
    float* h2n = h1n + (size_t)BB * NN * HH;

    const int UPD_SMEM = (64 * 65 + 2 * 64 * 97) * 4;
    cudaFuncSetAttribute(update_kernel, cudaFuncAttributeMaxDynamicSharedMemorySize, UPD_SMEM);

    mask_pack_kernel<<<dim3(NN / 4, 6), 128>>>(m00, m20, m01, m11, m12, m22);
    proj_norm_kernel<<<dim3(ROWS / 64, 9), 256>>>(h0, h1, h2, Wq, Wk);
    conv_v_kernel<<<dim3(ROWS * HH / 4 / 256, 3), 256>>>(h0, h1, h2);
    attn_mma_kernel<<<dim3(NN / 128, NSPLIT, 6), 128>>>();
    update_kernel<<<dim3(ROWS / 64, 3), 256, UPD_SMEM>>>(x0, h0, h1, h2,
                                                         Wsu0, Wsu12, Wdt, bdt,
                                                         stepp, oscal,
                                                         out2, h0n, h1n, h2n);
}